// round 1
// baseline (speedup 1.0000x reference)
#include <cuda_runtime.h>

// ---------------- scratch (no allocations allowed) ----------------
#define MAXN 16384
#define MAXE 1048576

__device__ int g_is64;                 // 1 if edge_index is int64, 0 if int32
__device__ int g_counts[MAXN];
__device__ int g_offsets[MAXN + 1];
__device__ int g_cursor[MAXN];
__device__ int g_beid[MAXE];           // edge id per CSR slot
__device__ int g_bcol[MAXE];           // source node per CSR slot

__device__ __forceinline__ int load_idx(const void* p, long i, int is64) {
    if (is64) return (int)(((const long long*)p)[i]);
    return ((const int*)p)[i];
}

// K0: zero counters; block 0 detects int32 vs int64 edge_index.
// If data is int64 (values < 2^31, nonneg), every odd 32-bit word is 0.
__global__ void k0_init(const int* ei_words, int n) {
    for (int i = blockIdx.x * blockDim.x + threadIdx.x; i < n;
         i += gridDim.x * blockDim.x) {
        g_counts[i] = 0;
    }
    if (blockIdx.x == 0) {
        __shared__ int any_nonzero;
        if (threadIdx.x == 0) any_nonzero = 0;
        __syncthreads();
        // check odd words 1,3,...,511 (256 samples)
        int w = ei_words[2 * threadIdx.x + 1];
        if (w != 0) atomicOr(&any_nonzero, 1);
        __syncthreads();
        if (threadIdx.x == 0) g_is64 = any_nonzero ? 0 : 1;
    }
}

// K1: histogram of destination nodes
__global__ void k1_count(const void* ei, long E) {
    long i = (long)blockIdx.x * blockDim.x + threadIdx.x;
    if (i < E) {
        int r = load_idx(ei, i, g_is64);
        atomicAdd(&g_counts[r], 1);
    }
}

// K2: single-block exclusive scan counts -> offsets; cursor = offsets
__global__ void k2_scan(int n) {
    __shared__ int sh[1024];
    int running = 0;
    for (int base = 0; base < n; base += 1024) {
        int i = base + threadIdx.x;
        int v = (i < n) ? g_counts[i] : 0;
        sh[threadIdx.x] = v;
        __syncthreads();
        for (int off = 1; off < 1024; off <<= 1) {
            int t = (threadIdx.x >= off) ? sh[threadIdx.x - off] : 0;
            __syncthreads();
            sh[threadIdx.x] += t;
            __syncthreads();
        }
        int incl = sh[threadIdx.x];
        int excl = incl - v + running;
        if (i < n) {
            g_offsets[i] = excl;
            g_cursor[i]  = excl;
        }
        running += sh[1023];
        __syncthreads();
    }
    if (threadIdx.x == 0) g_offsets[n] = running;
}

// K3: scatter edge ids + source cols into CSR buckets
__global__ void k3_fill(const void* ei, long E) {
    long i = (long)blockIdx.x * blockDim.x + threadIdx.x;
    if (i < E) {
        int is64 = g_is64;
        int r = load_idx(ei, i, is64);
        int c = load_idx(ei, E + i, is64);
        int pos = atomicAdd(&g_cursor[r], 1);
        g_beid[pos] = (int)i;
        g_bcol[pos] = c;
    }
}

__device__ __forceinline__ void acc4(float4& a, const float4 v) {
    a.x += v.x; a.y += v.y; a.z += v.z; a.w += v.w;
}

// K4: one block (2 warps) per node.
// warp 0: sum of x[col[e]] (gather, L2-resident) + copy x row
// warp 1: sum of edge_attr[e] (HBM stream)
__global__ void __launch_bounds__(64) k4_agg(const float* __restrict__ x,
                                             const float* __restrict__ ea,
                                             float* __restrict__ out) {
    int n   = blockIdx.x;
    int lid = threadIdx.x & 31;
    int w   = threadIdx.x >> 5;
    int beg = g_offsets[n];
    int end = g_offsets[n + 1];

    float4 a0 = make_float4(0.f, 0.f, 0.f, 0.f);
    float4 a1 = a0, a2 = a0, a3 = a0;

    if (w == 0) {
        int j = beg;
        for (; j + 4 <= end; j += 4) {
            int c0 = g_bcol[j];
            int c1 = g_bcol[j + 1];
            int c2 = g_bcol[j + 2];
            int c3 = g_bcol[j + 3];
            float4 v0 = __ldg((const float4*)(x + (long)c0 * 128) + lid);
            float4 v1 = __ldg((const float4*)(x + (long)c1 * 128) + lid);
            float4 v2 = __ldg((const float4*)(x + (long)c2 * 128) + lid);
            float4 v3 = __ldg((const float4*)(x + (long)c3 * 128) + lid);
            acc4(a0, v0); acc4(a1, v1); acc4(a2, v2); acc4(a3, v3);
        }
        for (; j < end; ++j) {
            int c = g_bcol[j];
            acc4(a0, __ldg((const float4*)(x + (long)c * 128) + lid));
        }
    } else {
        int j = beg;
        for (; j + 4 <= end; j += 4) {
            int e0 = g_beid[j];
            int e1 = g_beid[j + 1];
            int e2 = g_beid[j + 2];
            int e3 = g_beid[j + 3];
            float4 v0 = __ldg((const float4*)(ea + (long)e0 * 128) + lid);
            float4 v1 = __ldg((const float4*)(ea + (long)e1 * 128) + lid);
            float4 v2 = __ldg((const float4*)(ea + (long)e2 * 128) + lid);
            float4 v3 = __ldg((const float4*)(ea + (long)e3 * 128) + lid);
            acc4(a0, v0); acc4(a1, v1); acc4(a2, v2); acc4(a3, v3);
        }
        for (; j < end; ++j) {
            int e = g_beid[j];
            acc4(a0, __ldg((const float4*)(ea + (long)e * 128) + lid));
        }
    }

    float4 s;
    s.x = (a0.x + a1.x) + (a2.x + a3.x);
    s.y = (a0.y + a1.y) + (a2.y + a3.y);
    s.z = (a0.z + a1.z) + (a2.z + a3.z);
    s.w = (a0.w + a1.w) + (a2.w + a3.w);

    int deg = end - beg;
    float inv = 1.0f / (float)(deg > 0 ? deg : 1);
    s.x *= inv; s.y *= inv; s.z *= inv; s.w *= inv;

    long ob = (long)n * 384;
    if (w == 0) {
        float4 xv = __ldg((const float4*)(x + (long)n * 128) + lid);
        ((float4*)(out + ob))[lid]       = xv;  // out[:,0:128]   = x
        ((float4*)(out + ob + 128))[lid] = s;   // out[:,128:256] = mean x-gather
    } else {
        ((float4*)(out + ob + 256))[lid] = s;   // out[:,256:384] = mean edge_attr
    }
}

extern "C" void kernel_launch(void* const* d_in, const int* in_sizes, int n_in,
                              void* d_out, int out_size) {
    const float* x  = (const float*)d_in[0];
    const void*  ei = d_in[1];            // edge_index [2,E], int32 or int64
    const float* ea = (const float*)d_in[2];
    float* out = (float*)d_out;

    int  N = in_sizes[0] / 128;           // node count
    long E = (long)in_sizes[1] / 2;       // edge count (dtype-independent)

    const int TB = 256;
    int eb = (int)((E + TB - 1) / TB);

    k0_init<<<64, TB>>>((const int*)ei, N);
    k1_count<<<eb, TB>>>(ei, E);
    k2_scan<<<1, 1024>>>(N);
    k3_fill<<<eb, TB>>>(ei, E);
    k4_agg<<<N, 64>>>(x, ea, out);
}

// round 2
// speedup vs baseline: 1.0831x; 1.0831x over previous
#include <cuda_runtime.h>

// ---------------- scratch (no allocations allowed) ----------------
#define MAXN 16384
#define MAXE 1048576

__device__ int  g_is64;                // 1 if edge_index is int64, 0 if int32
__device__ int  g_counts[MAXN];
__device__ int  g_offsets[MAXN + 1];
__device__ int  g_cursor[MAXN];
__device__ int2 g_pack[MAXE];          // {edge id, source col} per CSR slot

__device__ __forceinline__ int load_idx(const void* p, long i, int is64) {
    if (is64) return (int)(((const long long*)p)[i]);
    return ((const int*)p)[i];
}

// K0: zero counters; block 0 detects int32 vs int64 edge_index.
// int64 node ids < 2^31 => every odd 32-bit word is 0 (256 samples).
__global__ void k0_init(const int* ei_words, int n) {
    for (int i = blockIdx.x * blockDim.x + threadIdx.x; i < n;
         i += gridDim.x * blockDim.x) {
        g_counts[i] = 0;
    }
    if (blockIdx.x == 0) {
        __shared__ int any_nonzero;
        if (threadIdx.x == 0) any_nonzero = 0;
        __syncthreads();
        int w = ei_words[2 * threadIdx.x + 1];
        if (w != 0) atomicOr(&any_nonzero, 1);
        __syncthreads();
        if (threadIdx.x == 0) g_is64 = any_nonzero ? 0 : 1;
    }
}

// K1: histogram of destination nodes, ILP-4
__global__ void k1_count(const void* ei, long E) {
    int is64 = g_is64;
    long base = (long)blockIdx.x * (blockDim.x * 4) + threadIdx.x;
    long s = blockDim.x;
    int r[4];
    bool ok[4];
#pragma unroll
    for (int u = 0; u < 4; u++) {
        long i = base + u * s;
        ok[u] = (i < E);
        r[u] = ok[u] ? load_idx(ei, i, is64) : 0;
    }
#pragma unroll
    for (int u = 0; u < 4; u++)
        if (ok[u]) atomicAdd(&g_counts[r[u]], 1);
}

// K2: chunked single-block exclusive scan (10 elems/thread in regs,
// one 1024-wide block scan). counts -> offsets; cursor = offsets.
#define SCAN_CHUNK 16
__global__ void k2_scan(int n) {
    const int T = 1024;
    int chunk = (n + T - 1) / T;           // <= SCAN_CHUNK
    int base = threadIdx.x * chunk;
    int local[SCAN_CHUNK];
    int sum = 0;
#pragma unroll
    for (int k = 0; k < SCAN_CHUNK; k++) {
        if (k < chunk) {
            int i = base + k;
            int v = (i < n) ? g_counts[i] : 0;
            local[k] = sum;               // exclusive-within-chunk
            sum += v;
        }
    }
    __shared__ int sh[T];
    sh[threadIdx.x] = sum;
    __syncthreads();
#pragma unroll
    for (int off = 1; off < T; off <<= 1) {
        int t = (threadIdx.x >= off) ? sh[threadIdx.x - off] : 0;
        __syncthreads();
        sh[threadIdx.x] += t;
        __syncthreads();
    }
    int excl_block = sh[threadIdx.x] - sum;
#pragma unroll
    for (int k = 0; k < SCAN_CHUNK; k++) {
        if (k < chunk) {
            int i = base + k;
            if (i < n) {
                int e = excl_block + local[k];
                g_offsets[i] = e;
                g_cursor[i]  = e;
            }
        }
    }
    if (threadIdx.x == T - 1) g_offsets[n] = excl_block + sum;
}

// K3: scatter {edge id, col} into CSR buckets, ILP-4, packed int2 store
__global__ void k3_fill(const void* ei, long E) {
    int is64 = g_is64;
    long base = (long)blockIdx.x * (blockDim.x * 4) + threadIdx.x;
    long s = blockDim.x;
    int r[4], c[4];
    bool ok[4];
#pragma unroll
    for (int u = 0; u < 4; u++) {
        long i = base + u * s;
        ok[u] = (i < E);
        r[u] = ok[u] ? load_idx(ei, i, is64) : 0;
        c[u] = ok[u] ? load_idx(ei, E + i, is64) : 0;
    }
    int pos[4];
#pragma unroll
    for (int u = 0; u < 4; u++)
        if (ok[u]) pos[u] = atomicAdd(&g_cursor[r[u]], 1);
#pragma unroll
    for (int u = 0; u < 4; u++)
        if (ok[u]) g_pack[pos[u]] = make_int2((int)(base + u * s), c[u]);
}

__device__ __forceinline__ void acc4(float4& a, const float4 v) {
    a.x += v.x; a.y += v.y; a.z += v.z; a.w += v.w;
}

// K4: one block (2 warps) per node.
// warp 0: sum of x[col[e]] (gather, L2-resident) + copy x row
// warp 1: sum of edge_attr[e] (HBM stream, streaming hint)
__global__ void __launch_bounds__(64) k4_agg(const float* __restrict__ x,
                                             const float* __restrict__ ea,
                                             float* __restrict__ out) {
    int n   = blockIdx.x;
    int lid = threadIdx.x & 31;
    int w   = threadIdx.x >> 5;
    int beg = g_offsets[n];
    int end = g_offsets[n + 1];

    float4 a0 = make_float4(0.f, 0.f, 0.f, 0.f);
    float4 a1 = a0, a2 = a0, a3 = a0;

    if (w == 0) {
        int j = beg;
        for (; j + 4 <= end; j += 4) {
            int2 p0 = g_pack[j];
            int2 p1 = g_pack[j + 1];
            int2 p2 = g_pack[j + 2];
            int2 p3 = g_pack[j + 3];
            float4 v0 = __ldg((const float4*)(x + (long)p0.y * 128) + lid);
            float4 v1 = __ldg((const float4*)(x + (long)p1.y * 128) + lid);
            float4 v2 = __ldg((const float4*)(x + (long)p2.y * 128) + lid);
            float4 v3 = __ldg((const float4*)(x + (long)p3.y * 128) + lid);
            acc4(a0, v0); acc4(a1, v1); acc4(a2, v2); acc4(a3, v3);
        }
        for (; j < end; ++j) {
            int2 p = g_pack[j];
            acc4(a0, __ldg((const float4*)(x + (long)p.y * 128) + lid));
        }
    } else {
        int j = beg;
        for (; j + 4 <= end; j += 4) {
            int2 p0 = g_pack[j];
            int2 p1 = g_pack[j + 1];
            int2 p2 = g_pack[j + 2];
            int2 p3 = g_pack[j + 3];
            float4 v0 = __ldcs((const float4*)(ea + (long)p0.x * 128) + lid);
            float4 v1 = __ldcs((const float4*)(ea + (long)p1.x * 128) + lid);
            float4 v2 = __ldcs((const float4*)(ea + (long)p2.x * 128) + lid);
            float4 v3 = __ldcs((const float4*)(ea + (long)p3.x * 128) + lid);
            acc4(a0, v0); acc4(a1, v1); acc4(a2, v2); acc4(a3, v3);
        }
        for (; j < end; ++j) {
            int2 p = g_pack[j];
            acc4(a0, __ldcs((const float4*)(ea + (long)p.x * 128) + lid));
        }
    }

    float4 s;
    s.x = (a0.x + a1.x) + (a2.x + a3.x);
    s.y = (a0.y + a1.y) + (a2.y + a3.y);
    s.z = (a0.z + a1.z) + (a2.z + a3.z);
    s.w = (a0.w + a1.w) + (a2.w + a3.w);

    int deg = end - beg;
    float inv = 1.0f / (float)(deg > 0 ? deg : 1);
    s.x *= inv; s.y *= inv; s.z *= inv; s.w *= inv;

    long ob = (long)n * 384;
    if (w == 0) {
        float4 xv = __ldg((const float4*)(x + (long)n * 128) + lid);
        ((float4*)(out + ob))[lid]       = xv;  // out[:,0:128]   = x
        ((float4*)(out + ob + 128))[lid] = s;   // out[:,128:256] = mean x-gather
    } else {
        ((float4*)(out + ob + 256))[lid] = s;   // out[:,256:384] = mean edge_attr
    }
}

extern "C" void kernel_launch(void* const* d_in, const int* in_sizes, int n_in,
                              void* d_out, int out_size) {
    const float* x  = (const float*)d_in[0];
    const void*  ei = d_in[1];            // edge_index [2,E], int32 or int64
    const float* ea = (const float*)d_in[2];
    float* out = (float*)d_out;

    int  N = in_sizes[0] / 128;           // node count
    long E = (long)in_sizes[1] / 2;       // edge count (dtype-independent)

    const int TB = 256;
    int eb4 = (int)((E + (long)TB * 4 - 1) / ((long)TB * 4));

    k0_init<<<64, TB>>>((const int*)ei, N);
    k1_count<<<eb4, TB>>>(ei, E);
    k2_scan<<<1, 1024>>>(N);
    k3_fill<<<eb4, TB>>>(ei, E);
    k4_agg<<<N, 64>>>(x, ea, out);
}

// round 3
// speedup vs baseline: 1.2363x; 1.1415x over previous
#include <cuda_runtime.h>

// ---------------- scratch (no allocations allowed) ----------------
#define MAXN 16384
#define MAXE 1048576

__device__ int  g_is64;                // 1 if edge_index is int64, 0 if int32
__device__ int  g_counts[MAXN];
__device__ int  g_offsets[MAXN + 1];
__device__ int  g_rank[MAXE];          // within-bucket rank per edge
__device__ int2 g_pack[MAXE];          // {edge id, source col} per CSR slot

__device__ __forceinline__ int load_idx(const void* p, long i, int is64) {
    if (is64) return (int)(((const long long*)p)[i]);
    return ((const int*)p)[i];
}

// K0: zero counters; block 0 detects int32 vs int64 edge_index.
// int64 node ids < 2^31 => every odd 32-bit word is 0 (256 samples).
__global__ void k0_init(const int* ei_words, int n) {
    for (int i = blockIdx.x * blockDim.x + threadIdx.x; i < n;
         i += gridDim.x * blockDim.x) {
        g_counts[i] = 0;
    }
    if (blockIdx.x == 0) {
        __shared__ int any_nonzero;
        if (threadIdx.x == 0) any_nonzero = 0;
        __syncthreads();
        int w = ei_words[2 * threadIdx.x + 1];
        if (w != 0) atomicOr(&any_nonzero, 1);
        __syncthreads();
        if (threadIdx.x == 0) g_is64 = any_nonzero ? 0 : 1;
    }
}

// K1: histogram of destinations; atomic result IS the within-bucket rank.
// Rank store is linear/coalesced -> no scattered dependent store here.
__global__ void k1_count(const void* ei, long E) {
    int is64 = g_is64;
    long base = (long)blockIdx.x * (blockDim.x * 4) + threadIdx.x;
    long s = blockDim.x;
    int r[4];
    bool ok[4];
#pragma unroll
    for (int u = 0; u < 4; u++) {
        long i = base + u * s;
        ok[u] = (i < E);
        r[u] = ok[u] ? load_idx(ei, i, is64) : 0;
    }
    int rk[4];
#pragma unroll
    for (int u = 0; u < 4; u++)
        if (ok[u]) rk[u] = atomicAdd(&g_counts[r[u]], 1);
#pragma unroll
    for (int u = 0; u < 4; u++)
        if (ok[u]) g_rank[base + u * s] = rk[u];
}

// K2: chunked single-block exclusive scan. counts -> offsets.
#define SCAN_CHUNK 16
__global__ void k2_scan(int n) {
    const int T = 1024;
    int chunk = (n + T - 1) / T;           // <= SCAN_CHUNK
    int base = threadIdx.x * chunk;
    int local[SCAN_CHUNK];
    int sum = 0;
#pragma unroll
    for (int k = 0; k < SCAN_CHUNK; k++) {
        if (k < chunk) {
            int i = base + k;
            int v = (i < n) ? g_counts[i] : 0;
            local[k] = sum;               // exclusive-within-chunk
            sum += v;
        }
    }
    __shared__ int sh[T];
    sh[threadIdx.x] = sum;
    __syncthreads();
#pragma unroll
    for (int off = 1; off < T; off <<= 1) {
        int t = (threadIdx.x >= off) ? sh[threadIdx.x - off] : 0;
        __syncthreads();
        sh[threadIdx.x] += t;
        __syncthreads();
    }
    int excl_block = sh[threadIdx.x] - sum;
#pragma unroll
    for (int k = 0; k < SCAN_CHUNK; k++) {
        if (k < chunk) {
            int i = base + k;
            if (i < n) g_offsets[i] = excl_block + local[k];
        }
    }
    if (threadIdx.x == T - 1) g_offsets[n] = excl_block + sum;
}

// K3: NO atomics. pos = offsets[r] + rank[i]; offsets (40KB) is L1-resident.
__global__ void k3_fill(const void* ei, long E) {
    int is64 = g_is64;
    long base = (long)blockIdx.x * (blockDim.x * 4) + threadIdx.x;
    long s = blockDim.x;
    int r[4], c[4], rk[4];
    bool ok[4];
#pragma unroll
    for (int u = 0; u < 4; u++) {
        long i = base + u * s;
        ok[u] = (i < E);
        r[u]  = ok[u] ? load_idx(ei, i, is64) : 0;
        c[u]  = ok[u] ? load_idx(ei, E + i, is64) : 0;
        rk[u] = ok[u] ? g_rank[i] : 0;
    }
#pragma unroll
    for (int u = 0; u < 4; u++) {
        if (ok[u]) {
            int pos = g_offsets[r[u]] + rk[u];
            g_pack[pos] = make_int2((int)(base + u * s), c[u]);
        }
    }
}

__device__ __forceinline__ void acc4(float4& a, const float4 v) {
    a.x += v.x; a.y += v.y; a.z += v.z; a.w += v.w;
}

// K4: one block (2 warps) per node.
// warp 0: sum of x[col[e]] (gather, L2-resident) + copy x row
// warp 1: sum of edge_attr[e] (HBM stream, streaming hint)
__global__ void __launch_bounds__(64) k4_agg(const float* __restrict__ x,
                                             const float* __restrict__ ea,
                                             float* __restrict__ out) {
    int n   = blockIdx.x;
    int lid = threadIdx.x & 31;
    int w   = threadIdx.x >> 5;
    int beg = g_offsets[n];
    int end = g_offsets[n + 1];

    float4 a0 = make_float4(0.f, 0.f, 0.f, 0.f);
    float4 a1 = a0, a2 = a0, a3 = a0;

    if (w == 0) {
        int j = beg;
        for (; j + 4 <= end; j += 4) {
            int2 p0 = g_pack[j];
            int2 p1 = g_pack[j + 1];
            int2 p2 = g_pack[j + 2];
            int2 p3 = g_pack[j + 3];
            float4 v0 = __ldg((const float4*)(x + (long)p0.y * 128) + lid);
            float4 v1 = __ldg((const float4*)(x + (long)p1.y * 128) + lid);
            float4 v2 = __ldg((const float4*)(x + (long)p2.y * 128) + lid);
            float4 v3 = __ldg((const float4*)(x + (long)p3.y * 128) + lid);
            acc4(a0, v0); acc4(a1, v1); acc4(a2, v2); acc4(a3, v3);
        }
        for (; j < end; ++j) {
            int2 p = g_pack[j];
            acc4(a0, __ldg((const float4*)(x + (long)p.y * 128) + lid));
        }
    } else {
        int j = beg;
        for (; j + 4 <= end; j += 4) {
            int2 p0 = g_pack[j];
            int2 p1 = g_pack[j + 1];
            int2 p2 = g_pack[j + 2];
            int2 p3 = g_pack[j + 3];
            float4 v0 = __ldcs((const float4*)(ea + (long)p0.x * 128) + lid);
            float4 v1 = __ldcs((const float4*)(ea + (long)p1.x * 128) + lid);
            float4 v2 = __ldcs((const float4*)(ea + (long)p2.x * 128) + lid);
            float4 v3 = __ldcs((const float4*)(ea + (long)p3.x * 128) + lid);
            acc4(a0, v0); acc4(a1, v1); acc4(a2, v2); acc4(a3, v3);
        }
        for (; j < end; ++j) {
            int2 p = g_pack[j];
            acc4(a0, __ldcs((const float4*)(ea + (long)p.x * 128) + lid));
        }
    }

    float4 s;
    s.x = (a0.x + a1.x) + (a2.x + a3.x);
    s.y = (a0.y + a1.y) + (a2.y + a3.y);
    s.z = (a0.z + a1.z) + (a2.z + a3.z);
    s.w = (a0.w + a1.w) + (a2.w + a3.w);

    int deg = end - beg;
    float inv = 1.0f / (float)(deg > 0 ? deg : 1);
    s.x *= inv; s.y *= inv; s.z *= inv; s.w *= inv;

    long ob = (long)n * 384;
    if (w == 0) {
        float4 xv = __ldg((const float4*)(x + (long)n * 128) + lid);
        ((float4*)(out + ob))[lid]       = xv;  // out[:,0:128]   = x
        ((float4*)(out + ob + 128))[lid] = s;   // out[:,128:256] = mean x-gather
    } else {
        ((float4*)(out + ob + 256))[lid] = s;   // out[:,256:384] = mean edge_attr
    }
}

extern "C" void kernel_launch(void* const* d_in, const int* in_sizes, int n_in,
                              void* d_out, int out_size) {
    const float* x  = (const float*)d_in[0];
    const void*  ei = d_in[1];            // edge_index [2,E], int32 or int64
    const float* ea = (const float*)d_in[2];
    float* out = (float*)d_out;

    int  N = in_sizes[0] / 128;           // node count
    long E = (long)in_sizes[1] / 2;       // edge count (dtype-independent)

    const int TB = 256;
    int eb4 = (int)((E + (long)TB * 4 - 1) / ((long)TB * 4));

    k0_init<<<64, TB>>>((const int*)ei, N);
    k1_count<<<eb4, TB>>>(ei, E);
    k2_scan<<<1, 1024>>>(N);
    k3_fill<<<eb4, TB>>>(ei, E);
    k4_agg<<<N, 64>>>(x, ea, out);
}